// round 2
// baseline (speedup 1.0000x reference)
#include <cuda_runtime.h>

#define NN 25000
#define EE 400000

// Scratch: Z[j][k][h], fp32, 25000 * 1024 floats = 102.4 MB
__device__ __align__(16) float g_Z[NN * 1024];
__device__ int g_cnt[NN];        // per-src degree
__device__ int g_off[NN + 1];    // CSR offsets (src-sorted)
__device__ int g_pos[NN];        // scatter cursors
__device__ int g_perm[EE];       // edge ids sorted by src

// ---------------------------------------------------------------------------
// Counting sort of edges by src: init -> hist -> scan -> scatter
// ---------------------------------------------------------------------------
__global__ void k_init() {
    int i = blockIdx.x * blockDim.x + threadIdx.x;
    if (i < NN) g_cnt[i] = 0;
}

__global__ void k_hist(const int* __restrict__ ei) {
    int e = blockIdx.x * blockDim.x + threadIdx.x;
    if (e < EE) atomicAdd(&g_cnt[ei[e]], 1);
}

__global__ void __launch_bounds__(1024) k_scan() {
    __shared__ int part[1024];
    const int t = threadIdx.x;
    const int beg = t * 25;
    const int end = (beg + 25 < NN) ? beg + 25 : NN;
    int s = 0;
    for (int i = beg; i < end; i++) s += g_cnt[i];
    part[t] = s;
    __syncthreads();
    // Hillis-Steele inclusive scan over 1024 partials
    for (int off = 1; off < 1024; off <<= 1) {
        int v = (t >= off) ? part[t - off] : 0;
        __syncthreads();
        part[t] += v;
        __syncthreads();
    }
    int run = (t == 0) ? 0 : part[t - 1];
    for (int i = beg; i < end; i++) {
        g_off[i] = run;
        g_pos[i] = run;
        run += g_cnt[i];
    }
    if (t == 0) g_off[NN] = part[1023];
}

__global__ void k_scatter(const int* __restrict__ ei) {
    int e = blockIdx.x * blockDim.x + threadIdx.x;
    if (e < EE) {
        int p = atomicAdd(&g_pos[ei[e]], 1);
        g_perm[p] = e;
    }
}

// ---------------------------------------------------------------------------
// K1: Z = x @ G where G[d][c] (c = k*32+h) = edge_W[(d*32+h)*32 + k]
//     plus out init: out = x @ node_W^T
// ---------------------------------------------------------------------------
__global__ void __launch_bounds__(256, 1)
k1_build_Z(const float* __restrict__ x, const float* __restrict__ edge_W,
           const float* __restrict__ node_W, float* __restrict__ out) {
    extern __shared__ float sm[];
    float* Gs  = sm;               // 32 rows x 1024 cols (swizzled), 128 KB
    float* xs  = Gs + 32 * 1024;   // x transposed [32][72]
    float* nws = xs + 32 * 72;     // node_W [32][33]

    const int t  = threadIdx.x;
    const int tx = t & 31;
    const int ty = t >> 5;
    const int node0 = blockIdx.x * 64;

    for (int i = t; i < 32 * 1024; i += 256) {
        const int d   = i >> 10;
        const int rem = i & 1023;
        const int h   = rem >> 5;
        const int k   = rem & 31;
        const int cb  = ((k << 5) | h) << 2;
        const int sw  = cb ^ ((cb >> 3) & 0x70);
        Gs[(d << 10) + (sw >> 2)] = edge_W[i];
    }
    for (int i = t; i < 64 * 8; i += 256) {
        const int jl = i >> 3;
        const int d4 = (i & 7) << 2;
        const int j  = node0 + jl;
        float4 v = make_float4(0.f, 0.f, 0.f, 0.f);
        if (j < NN) v = *reinterpret_cast<const float4*>(x + j * 32 + d4);
        xs[(d4 + 0) * 72 + jl] = v.x;
        xs[(d4 + 1) * 72 + jl] = v.y;
        xs[(d4 + 2) * 72 + jl] = v.z;
        xs[(d4 + 3) * 72 + jl] = v.w;
    }
    for (int i = t; i < 1024; i += 256) {
        nws[(i >> 5) * 33 + (i & 31)] = node_W[i];
    }
    __syncthreads();

    // out init: warp ty handles nodes node0+ty*8..+7, lane tx = h
    {
        float accn[8];
#pragma unroll
        for (int n = 0; n < 8; n++) accn[n] = 0.f;
#pragma unroll 4
        for (int d = 0; d < 32; d++) {
            const float w = nws[tx * 33 + d];
#pragma unroll
            for (int n = 0; n < 8; n++)
                accn[n] += xs[d * 72 + ty * 8 + n] * w;
        }
#pragma unroll
        for (int n = 0; n < 8; n++) {
            const int j = node0 + ty * 8 + n;
            if (j < NN) out[j * 32 + tx] = accn[n];
        }
    }

    // Main Z GEMM: 8 col-tiles of 128; each thread: 8 nodes x 4 cols
    for (int tile = 0; tile < 8; tile++) {
        const int c   = tile * 128 + tx * 4;
        const int cb  = c << 2;
        const int swi = (cb ^ ((cb >> 3) & 0x70)) >> 2;
        float acc[8][4];
#pragma unroll
        for (int n = 0; n < 8; n++)
#pragma unroll
            for (int i = 0; i < 4; i++) acc[n][i] = 0.f;

#pragma unroll 4
        for (int d = 0; d < 32; d++) {
            const float4 b  = *reinterpret_cast<const float4*>(&Gs[(d << 10) + swi]);
            const float4 a0 = *reinterpret_cast<const float4*>(&xs[d * 72 + ty * 8]);
            const float4 a1 = *reinterpret_cast<const float4*>(&xs[d * 72 + ty * 8 + 4]);
            const float a[8] = {a0.x, a0.y, a0.z, a0.w, a1.x, a1.y, a1.z, a1.w};
#pragma unroll
            for (int n = 0; n < 8; n++) {
                acc[n][0] += a[n] * b.x;
                acc[n][1] += a[n] * b.y;
                acc[n][2] += a[n] * b.z;
                acc[n][3] += a[n] * b.w;
            }
        }
#pragma unroll
        for (int n = 0; n < 8; n++) {
            const int j = node0 + ty * 8 + n;
            if (j < NN)
                *reinterpret_cast<float4*>(&g_Z[j * 1024 + c]) =
                    make_float4(acc[n][0], acc[n][1], acc[n][2], acc[n][3]);
        }
    }
}

// ---------------------------------------------------------------------------
// K2 (sorted): one warp per SOURCE node. Z[j] row cached in registers
// (zr4[i] = float4 covering k = i*4 + (lane>>3), h-quad (lane&7)*4).
// Loop over this node's edges: 8 broadcast shfls of ea + 32 FFMA,
// butterfly over ^8/^16, lanes 0..7 emit red.global.add.v4.f32.
// ---------------------------------------------------------------------------
__global__ void __launch_bounds__(256)
k2_sorted(const float* __restrict__ ea, const int* __restrict__ ei,
          float* __restrict__ out) {
    const int j    = blockIdx.x * 8 + (threadIdx.x >> 5);
    const int lane = threadIdx.x & 31;
    if (j >= NN) return;

    const int beg = g_off[j];
    const int end = g_off[j + 1];
    if (beg == end) return;

    // Cache Z row in registers: zr4[i] = Zrow4[i*32 + lane]
    const float4* Zp = reinterpret_cast<const float4*>(g_Z + j * 1024);
    float4 zr4[8];
#pragma unroll
    for (int i = 0; i < 8; i++) zr4[i] = Zp[i * 32 + lane];

    for (int p = beg; p < end; p++) {
        const int e   = g_perm[p];
        const int dst = ei[EE + e];
        const float eav = ea[e * 32 + lane];

        float4 acc = make_float4(0.f, 0.f, 0.f, 0.f);
#pragma unroll
        for (int i = 0; i < 8; i++) {
            const float ek = __shfl_sync(0xffffffffu, eav, i * 4 + (lane >> 3));
            acc.x += ek * zr4[i].x;
            acc.y += ek * zr4[i].y;
            acc.z += ek * zr4[i].z;
            acc.w += ek * zr4[i].w;
        }
        acc.x += __shfl_xor_sync(0xffffffffu, acc.x, 8);
        acc.y += __shfl_xor_sync(0xffffffffu, acc.y, 8);
        acc.z += __shfl_xor_sync(0xffffffffu, acc.z, 8);
        acc.w += __shfl_xor_sync(0xffffffffu, acc.w, 8);
        acc.x += __shfl_xor_sync(0xffffffffu, acc.x, 16);
        acc.y += __shfl_xor_sync(0xffffffffu, acc.y, 16);
        acc.z += __shfl_xor_sync(0xffffffffu, acc.z, 16);
        acc.w += __shfl_xor_sync(0xffffffffu, acc.w, 16);

        if (lane < 8) {
            float* pdst = out + dst * 32 + lane * 4;
            asm volatile("red.global.add.v4.f32 [%0], {%1,%2,%3,%4};"
                         :: "l"(pdst), "f"(acc.x), "f"(acc.y), "f"(acc.z), "f"(acc.w)
                         : "memory");
        }
    }
}

// ---------------------------------------------------------------------------
extern "C" void kernel_launch(void* const* d_in, const int* in_sizes, int n_in,
                              void* d_out, int out_size) {
    const float* x          = (const float*)d_in[0];  // [25000,32]
    const float* edge_attr  = (const float*)d_in[1];  // [400000,32]
    const float* edge_W     = (const float*)d_in[2];  // [1024,32]
    const float* node_W     = (const float*)d_in[3];  // [32,32]
    const int*   edge_index = (const int*)d_in[4];    // [2,400000]
    float* out = (float*)d_out;

    const size_t smem1 = (32 * 1024 + 32 * 72 + 32 * 33) * sizeof(float); // 144.5 KB
    cudaFuncSetAttribute(k1_build_Z, cudaFuncAttributeMaxDynamicSharedMemorySize,
                         (int)smem1);

    k_init<<<(NN + 255) / 256, 256>>>();
    k_hist<<<(EE + 255) / 256, 256>>>(edge_index);
    k1_build_Z<<<(NN + 63) / 64, 256, smem1>>>(x, edge_W, node_W, out);
    k_scan<<<1, 1024>>>();
    k_scatter<<<(EE + 255) / 256, 256>>>(edge_index);
    k2_sorted<<<(NN + 7) / 8, 256>>>(edge_attr, edge_index, out);
}

// round 3
// speedup vs baseline: 1.6967x; 1.6967x over previous
#include <cuda_runtime.h>
#include <cuda_fp16.h>

#define NN 25000
#define EE 400000

// Z stored fp16, 25000 rows x 1024 halves = 51.2 MB (L2-resident).
// Row layout (chunked for K2): uint4 chunk index ci = i*32 + l (i=0..3, l=lane):
//   halves[0..3] = Z[k0, hq*4 .. hq*4+3],  halves[4..7] = Z[k0+4, same h-quad]
//   where k0 = 8*i + (l>>3), hq = (l&7).
__device__ __align__(16) __half g_Zh[NN * 1024];

// packed fp32x2 helpers (Blackwell PTX-only dual-FMA)
__device__ __forceinline__ unsigned long long pk2(float lo, float hi) {
    unsigned long long r;
    asm("mov.b64 %0, {%1,%2};" : "=l"(r) : "f"(lo), "f"(hi));
    return r;
}
__device__ __forceinline__ void upk2(float& lo, float& hi, unsigned long long v) {
    asm("mov.b64 {%0,%1}, %2;" : "=f"(lo), "=f"(hi) : "l"(v));
}
__device__ __forceinline__ unsigned long long ffma2(unsigned long long a,
                                                    unsigned long long b,
                                                    unsigned long long c) {
    unsigned long long d;
    asm("fma.rn.f32x2 %0, %1, %2, %3;" : "=l"(d) : "l"(a), "l"(b), "l"(c));
    return d;
}

// ---------------------------------------------------------------------------
// K1: Z = x @ G, G[d][k*32+h] = edge_W[(d*32+h)*32 + k]; Z stored fp16 in the
// chunked layout above. Also out = x @ node_W^T.
// 256 threads / 64 nodes. Inner GEMM uses fma.rn.f32x2 with node-pairs packed.
// ---------------------------------------------------------------------------
__global__ void __launch_bounds__(256, 1)
k1_build_Z(const float* __restrict__ x, const float* __restrict__ edge_W,
           const float* __restrict__ node_W, float* __restrict__ out) {
    extern __shared__ float sm[];
    float* Gs  = sm;               // 32 x 1024 swizzled, 128 KB
    float* xs  = Gs + 32 * 1024;   // x transposed [32][72]
    float* nws = xs + 32 * 72;     // node_W [32][33]

    const int t  = threadIdx.x;
    const int tx = t & 31;
    const int ty = t >> 5;
    const int node0 = blockIdx.x * 64;

    for (int i = t; i < 32 * 1024; i += 256) {
        const int d   = i >> 10;
        const int rem = i & 1023;
        const int h   = rem >> 5;
        const int k   = rem & 31;
        const int cb  = ((k << 5) | h) << 2;
        const int sw  = cb ^ ((cb >> 3) & 0x70);
        Gs[(d << 10) + (sw >> 2)] = edge_W[i];
    }
    for (int i = t; i < 64 * 8; i += 256) {
        const int jl = i >> 3;
        const int d4 = (i & 7) << 2;
        const int j  = node0 + jl;
        float4 v = make_float4(0.f, 0.f, 0.f, 0.f);
        if (j < NN) v = *reinterpret_cast<const float4*>(x + j * 32 + d4);
        xs[(d4 + 0) * 72 + jl] = v.x;
        xs[(d4 + 1) * 72 + jl] = v.y;
        xs[(d4 + 2) * 72 + jl] = v.z;
        xs[(d4 + 3) * 72 + jl] = v.w;
    }
    for (int i = t; i < 1024; i += 256) {
        nws[(i >> 5) * 33 + (i & 31)] = node_W[i];
    }
    __syncthreads();

    // out init: warp ty -> nodes node0+ty*8..+7, lane tx = h
    {
        float accn[8];
#pragma unroll
        for (int n = 0; n < 8; n++) accn[n] = 0.f;
#pragma unroll 4
        for (int d = 0; d < 32; d++) {
            const float w = nws[tx * 33 + d];
#pragma unroll
            for (int n = 0; n < 8; n++)
                accn[n] += xs[d * 72 + ty * 8 + n] * w;
        }
#pragma unroll
        for (int n = 0; n < 8; n++) {
            const int j = node0 + ty * 8 + n;
            if (j < NN) out[j * 32 + tx] = accn[n];
        }
    }

    // Main Z GEMM: 8 col-tiles of 128 (col c = k*32+h space, thread owns
    // k = tile*4 + (tx>>3), h-quad = (tx&7)*4). Node-pairs packed in f32x2.
    for (int tile = 0; tile < 8; tile++) {
        const int c   = tile * 128 + tx * 4;
        const int cb  = c << 2;
        const int swi = (cb ^ ((cb >> 3) & 0x70)) >> 2;

        unsigned long long acc2[4][4];   // [node-pair][col]
#pragma unroll
        for (int np = 0; np < 4; np++)
#pragma unroll
            for (int i = 0; i < 4; i++) acc2[np][i] = 0ull;

#pragma unroll 4
        for (int d = 0; d < 32; d++) {
            const float4 b = *reinterpret_cast<const float4*>(&Gs[(d << 10) + swi]);
            const unsigned long long bc[4] = {pk2(b.x, b.x), pk2(b.y, b.y),
                                              pk2(b.z, b.z), pk2(b.w, b.w)};
            const unsigned long long* ap =
                reinterpret_cast<const unsigned long long*>(&xs[d * 72 + ty * 8]);
#pragma unroll
            for (int np = 0; np < 4; np++) {
                const unsigned long long a2 = ap[np];
#pragma unroll
                for (int i = 0; i < 4; i++)
                    acc2[np][i] = ffma2(a2, bc[i], acc2[np][i]);
            }
        }

        // Store fp16 into chunked layout: uint2 slot = (i*32+tx)*2 + (tile&1),
        // i = tile>>1  (tile even -> k0 halves, tile odd -> k0+4 halves)
        const int slot = ((tile >> 1) * 32 + tx) * 2 + (tile & 1);
#pragma unroll
        for (int np = 0; np < 4; np++) {
#pragma unroll
            for (int s = 0; s < 2; s++) {
                const int n = np * 2 + s;
                const int j = node0 + ty * 8 + n;
                if (j < NN) {
                    float v0, v1, v2, v3, dummy;
                    if (s == 0) {
                        upk2(v0, dummy, acc2[np][0]);
                        upk2(v1, dummy, acc2[np][1]);
                        upk2(v2, dummy, acc2[np][2]);
                        upk2(v3, dummy, acc2[np][3]);
                    } else {
                        upk2(dummy, v0, acc2[np][0]);
                        upk2(dummy, v1, acc2[np][1]);
                        upk2(dummy, v2, acc2[np][2]);
                        upk2(dummy, v3, acc2[np][3]);
                    }
                    __half2 h01 = __floats2half2_rn(v0, v1);
                    __half2 h23 = __floats2half2_rn(v2, v3);
                    uint2 pkd = make_uint2(*reinterpret_cast<unsigned*>(&h01),
                                           *reinterpret_cast<unsigned*>(&h23));
                    reinterpret_cast<uint2*>(g_Zh)[j * 256 + slot] = pkd;
                }
            }
        }
    }
}

// ---------------------------------------------------------------------------
// K2: warp per edge. Z[src] row (2KB fp16) gathered with 4x LDG.128.
// Chunk i gives lane l: k0=8i+(l>>3), k0+4, h-quad (l&7)*4.
// Butterfly ^8,^16 completes the k-sum; lanes 0..7 emit red.global.add.v4.f32.
// ---------------------------------------------------------------------------
__global__ void __launch_bounds__(256)
k2_edges(const float* __restrict__ ea, const int* __restrict__ ei,
         float* __restrict__ out) {
    const int e    = blockIdx.x * 8 + (threadIdx.x >> 5);
    const int lane = threadIdx.x & 31;
    if (e >= EE) return;

    const int src = ei[e];
    const int dst = ei[EE + e];
    const float eav = ea[e * 32 + lane];

    const uint4* Zp = reinterpret_cast<const uint4*>(g_Zh + src * 1024);
    const int kres = lane >> 3;
    float4 acc = make_float4(0.f, 0.f, 0.f, 0.f);
#pragma unroll
    for (int i = 0; i < 4; i++) {
        const uint4 z = Zp[i * 32 + lane];
        const float ek0 = __shfl_sync(0xffffffffu, eav, i * 8 + kres);
        const float ek1 = __shfl_sync(0xffffffffu, eav, i * 8 + 4 + kres);
        const float2 f01 = __half22float2(*reinterpret_cast<const __half2*>(&z.x));
        const float2 f23 = __half22float2(*reinterpret_cast<const __half2*>(&z.y));
        const float2 g01 = __half22float2(*reinterpret_cast<const __half2*>(&z.z));
        const float2 g23 = __half22float2(*reinterpret_cast<const __half2*>(&z.w));
        acc.x += ek0 * f01.x + ek1 * g01.x;
        acc.y += ek0 * f01.y + ek1 * g01.y;
        acc.z += ek0 * f23.x + ek1 * g23.x;
        acc.w += ek0 * f23.y + ek1 * g23.y;
    }
    acc.x += __shfl_xor_sync(0xffffffffu, acc.x, 8);
    acc.y += __shfl_xor_sync(0xffffffffu, acc.y, 8);
    acc.z += __shfl_xor_sync(0xffffffffu, acc.z, 8);
    acc.w += __shfl_xor_sync(0xffffffffu, acc.w, 8);
    acc.x += __shfl_xor_sync(0xffffffffu, acc.x, 16);
    acc.y += __shfl_xor_sync(0xffffffffu, acc.y, 16);
    acc.z += __shfl_xor_sync(0xffffffffu, acc.z, 16);
    acc.w += __shfl_xor_sync(0xffffffffu, acc.w, 16);

    if (lane < 8) {
        float* p = out + dst * 32 + lane * 4;
        asm volatile("red.global.add.v4.f32 [%0], {%1,%2,%3,%4};"
                     :: "l"(p), "f"(acc.x), "f"(acc.y), "f"(acc.z), "f"(acc.w)
                     : "memory");
    }
}

// ---------------------------------------------------------------------------
extern "C" void kernel_launch(void* const* d_in, const int* in_sizes, int n_in,
                              void* d_out, int out_size) {
    const float* x          = (const float*)d_in[0];  // [25000,32]
    const float* edge_attr  = (const float*)d_in[1];  // [400000,32]
    const float* edge_W     = (const float*)d_in[2];  // [1024,32]
    const float* node_W     = (const float*)d_in[3];  // [32,32]
    const int*   edge_index = (const int*)d_in[4];    // [2,400000]
    float* out = (float*)d_out;

    const size_t smem1 = (32 * 1024 + 32 * 72 + 32 * 33) * sizeof(float); // 144.5 KB
    cudaFuncSetAttribute(k1_build_Z, cudaFuncAttributeMaxDynamicSharedMemorySize,
                         (int)smem1);

    k1_build_Z<<<(NN + 63) / 64, 256, smem1>>>(x, edge_W, node_W, out);
    k2_edges<<<EE / 8, 256>>>(edge_attr, edge_index, out);
}